// round 4
// baseline (speedup 1.0000x reference)
#include <cuda_runtime.h>
#include <math.h>

#define NB 8
#define NM 8192
#define ND 256
#define SLICE ((long)NB * NM * ND)   // 16,777,216 elements per hop slice

// Persistent scratch (device globals — no allocation allowed).
__device__ float g_u[NB * ND];        // running query vector u
__device__ float g_ok[NB * ND];       // per-hop o_k accumulator
__device__ float g_logits[NB * NM];   // intermediate logits (hops 0,1)
__device__ float g_w[NB * NM];        // softmax * gp weights

// ---------------------------------------------------------------------------
// init: u = query_vector, o_k = 0  (must run every graph replay)
// ---------------------------------------------------------------------------
__global__ void init_kernel(const float* __restrict__ q) {
    int i = blockIdx.x * blockDim.x + threadIdx.x;
    if (i < NB * ND) {
        g_u[i]  = q[i];
        g_ok[i] = 0.0f;
    }
}

// ---------------------------------------------------------------------------
// pass_a: logits[b,m] = gp[b,m] * dot(S[b,m,:], u[b,:])
// 1 warp per row, float4 loads (each lane: 2×float4 = 8 elems), warp reduce.
// 8 rows / block of 256 threads -> grid 8192.
// logits_out == nullptr  ->  write to internal g_logits.
// ---------------------------------------------------------------------------
__global__ __launch_bounds__(256) void pass_a(const float* __restrict__ S,
                                              const float* __restrict__ gp,
                                              float* logits_out) {
    __shared__ float us[ND];
    int b = blockIdx.x >> 10;                 // 1024 blocks per batch
    us[threadIdx.x] = g_u[b * ND + threadIdx.x];
    __syncthreads();

    int warp = threadIdx.x >> 5;
    int lane = threadIdx.x & 31;
    long row = (long)blockIdx.x * 8 + warp;   // global (b,m) row in [0, 65536)

    const float4* Sr = (const float4*)(S + row * ND);
    const float4* u4 = (const float4*)us;

    float4 a = Sr[lane];        // d = lane*4 .. lane*4+3
    float4 c = Sr[lane + 32];   // d = 128 + lane*4 ..
    float4 ua = u4[lane];
    float4 uc = u4[lane + 32];

    float s = a.x * ua.x + a.y * ua.y + a.z * ua.z + a.w * ua.w
            + c.x * uc.x + c.y * uc.y + c.z * uc.z + c.w * uc.w;

    #pragma unroll
    for (int off = 16; off; off >>= 1)
        s += __shfl_xor_sync(0xffffffffu, s, off);

    if (lane == 0) {
        float* dst = logits_out ? logits_out : g_logits;
        dst[row] = gp[row] * s;               // gp is (B,M) flat == row index
    }
}

// ---------------------------------------------------------------------------
// softmax over m per batch; writes w = p * gp (always) and p to p_out (last hop).
// logits_in == nullptr -> read internal g_logits.
// 1 block per batch, 1024 threads, 8 elems/thread.
// ---------------------------------------------------------------------------
__global__ __launch_bounds__(1024) void softmax_kernel(const float* logits_in,
                                                       const float* __restrict__ gp,
                                                       float* p_out) {
    __shared__ float red_max[32];
    __shared__ float red_sum[32];
    int b   = blockIdx.x;
    int tid = threadIdx.x;
    const float* logits = logits_in ? logits_in : g_logits;

    float l[8];
    float mx = -INFINITY;
    #pragma unroll
    for (int k = 0; k < 8; k++) {
        l[k] = logits[b * NM + tid + k * 1024];
        mx = fmaxf(mx, l[k]);
    }
    #pragma unroll
    for (int off = 16; off; off >>= 1)
        mx = fmaxf(mx, __shfl_xor_sync(0xffffffffu, mx, off));
    if ((tid & 31) == 0) red_max[tid >> 5] = mx;
    __syncthreads();
    if (tid < 32) {
        float v = red_max[tid];
        #pragma unroll
        for (int off = 16; off; off >>= 1)
            v = fmaxf(v, __shfl_xor_sync(0xffffffffu, v, off));
        red_max[tid] = v;
    }
    __syncthreads();
    mx = red_max[0];

    float sum = 0.0f;
    #pragma unroll
    for (int k = 0; k < 8; k++) {
        l[k] = __expf(l[k] - mx);
        sum += l[k];
    }
    #pragma unroll
    for (int off = 16; off; off >>= 1)
        sum += __shfl_xor_sync(0xffffffffu, sum, off);
    if ((tid & 31) == 0) red_sum[tid >> 5] = sum;
    __syncthreads();
    if (tid < 32) {
        float v = red_sum[tid];
        #pragma unroll
        for (int off = 16; off; off >>= 1)
            v += __shfl_xor_sync(0xffffffffu, v, off);
        red_sum[tid] = v;
    }
    __syncthreads();
    float inv = 1.0f / red_sum[0];

    #pragma unroll
    for (int k = 0; k < 8; k++) {
        int idx = b * NM + tid + k * 1024;
        float p = l[k] * inv;
        if (p_out) p_out[idx] = p;
        g_w[idx] = p * gp[idx];
    }
}

// ---------------------------------------------------------------------------
// pass_c: o_k[b,d] += sum over 64-row chunk of w[b,m] * S[b,m,d]
// 256 threads, thread = d column; fully-unrolled 64-row FMA stream; RED at end.
// grid = 8 * 128 = 1024 blocks.
// ---------------------------------------------------------------------------
__global__ __launch_bounds__(256) void pass_c(const float* __restrict__ S) {
    __shared__ float ws[64];
    int b  = blockIdx.x >> 7;                 // 128 chunks per batch
    int m0 = (blockIdx.x & 127) * 64;
    if (threadIdx.x < 64)
        ws[threadIdx.x] = g_w[b * NM + m0 + threadIdx.x];
    __syncthreads();

    const float* Sp = S + ((long)b * NM + m0) * ND + threadIdx.x;
    float acc = 0.0f;
    #pragma unroll 16
    for (int r = 0; r < 64; r++)
        acc = fmaf(ws[r], Sp[(long)r * ND], acc);

    atomicAdd(&g_ok[b * ND + threadIdx.x], acc);
}

// ---------------------------------------------------------------------------
// fold: u += o_k, then zero o_k for the next hop.
// ---------------------------------------------------------------------------
__global__ void fold_kernel() {
    int i = blockIdx.x * blockDim.x + threadIdx.x;
    if (i < NB * ND) {
        g_u[i] += g_ok[i];
        g_ok[i] = 0.0f;
    }
}

// ---------------------------------------------------------------------------
// launcher — pure kernel launches, no host API calls (graph-capture safe).
// ---------------------------------------------------------------------------
extern "C" void kernel_launch(void* const* d_in, const int* in_sizes, int n_in,
                              void* d_out, int out_size) {
    // Map inputs by element count (distinct sizes): 2048=query, 65536=gp, rest=m_story
    const float* q  = nullptr;
    const float* gp = nullptr;
    const float* S  = nullptr;
    for (int i = 0; i < n_in; i++) {
        if (in_sizes[i] == NB * ND)      q  = (const float*)d_in[i];
        else if (in_sizes[i] == NB * NM) gp = (const float*)d_in[i];
        else                             S  = (const float*)d_in[i];
    }

    float* out   = (float*)d_out;
    float* p_out = out;            // prob_soft   -> first 65536
    float* l_out = out + NB * NM;  // prob_logits -> second 65536

    init_kernel<<<2, 1024>>>(q);

    // hop 0
    pass_a<<<8192, 256>>>(S,            gp, nullptr);
    softmax_kernel<<<NB, 1024>>>(nullptr, gp, nullptr);
    pass_c<<<1024, 256>>>(S + SLICE);
    fold_kernel<<<2, 1024>>>();

    // hop 1
    pass_a<<<8192, 256>>>(S + SLICE,    gp, nullptr);
    softmax_kernel<<<NB, 1024>>>(nullptr, gp, nullptr);
    pass_c<<<1024, 256>>>(S + 2 * SLICE);
    fold_kernel<<<2, 1024>>>();

    // hop 2 — outputs only need logits + softmax; m_story[3] never touched.
    pass_a<<<8192, 256>>>(S + 2 * SLICE, gp, l_out);
    softmax_kernel<<<NB, 1024>>>(l_out,  gp, p_out);
}

// round 7
// speedup vs baseline: 1.1156x; 1.1156x over previous
#include <cuda_runtime.h>
#include <math.h>

#define NB 8
#define NM 8192
#define ND 256
#define SLICE ((long)NB * NM * ND)   // 16,777,216 elements per hop slice

// Persistent scratch (device globals — no allocation allowed).
__device__ float g_ok0[NB * ND];      // o_k from hop 0
__device__ float g_ok1[NB * ND];      // o_k from hop 1
__device__ float g_logits[NB * NM];   // intermediate logits (hops 0,1)
__device__ float g_w[NB * NM];        // softmax * gp weights

// ---------------------------------------------------------------------------
// init: zero both o_k accumulators (must run every graph replay)
// ---------------------------------------------------------------------------
__global__ void init_kernel() {
    int i = blockIdx.x * blockDim.x + threadIdx.x;
    if (i < NB * ND) {
        g_ok0[i] = 0.0f;
        g_ok1[i] = 0.0f;
    }
}

// ---------------------------------------------------------------------------
// pass_a: logits[b,m] = gp[b,m] * dot(S[b,m,:], u[b,:])
//   u = q (+ ok0 if hop>=1) (+ ok1 if hop>=2)   -- fold fused in.
// 1 warp handles 2 rows; 8 warps/block -> 16 rows/block -> 4096 blocks.
// Each lane: 4 float4 loads in flight (256B).
// logits_out == nullptr -> write internal g_logits.
// ---------------------------------------------------------------------------
__global__ __launch_bounds__(256) void pass_a(const float* __restrict__ S,
                                              const float* __restrict__ gp,
                                              const float* __restrict__ q,
                                              int hop,
                                              float* logits_out) {
    __shared__ float us[ND];
    int tid = threadIdx.x;
    int b = blockIdx.x >> 9;                  // 512 blocks per batch
    float uv = q[b * ND + tid];
    if (hop >= 1) uv += g_ok0[b * ND + tid];
    if (hop >= 2) uv += g_ok1[b * ND + tid];
    us[tid] = uv;
    __syncthreads();

    int warp = tid >> 5;
    int lane = tid & 31;
    long row0 = (long)blockIdx.x * 16 + warp * 2;

    const float4* u4 = (const float4*)us;
    float4 ua = u4[lane];
    float4 uc = u4[lane + 32];

    const float4* S0 = (const float4*)(S + row0 * ND);
    const float4* S1 = (const float4*)(S + (row0 + 1) * ND);
    float4 a0 = S0[lane];
    float4 c0 = S0[lane + 32];
    float4 a1 = S1[lane];
    float4 c1 = S1[lane + 32];

    float s0 = a0.x * ua.x + a0.y * ua.y + a0.z * ua.z + a0.w * ua.w
             + c0.x * uc.x + c0.y * uc.y + c0.z * uc.z + c0.w * uc.w;
    float s1 = a1.x * ua.x + a1.y * ua.y + a1.z * ua.z + a1.w * ua.w
             + c1.x * uc.x + c1.y * uc.y + c1.z * uc.z + c1.w * uc.w;

    #pragma unroll
    for (int off = 16; off; off >>= 1) {
        s0 += __shfl_xor_sync(0xffffffffu, s0, off);
        s1 += __shfl_xor_sync(0xffffffffu, s1, off);
    }

    if (lane == 0) {
        float* dst = logits_out ? logits_out : g_logits;
        dst[row0]     = gp[row0]     * s0;
        dst[row0 + 1] = gp[row0 + 1] * s1;
    }
}

// ---------------------------------------------------------------------------
// softmax over m per batch; writes w = p * gp (always) and p to p_out (last hop).
// logits_in == nullptr -> read internal g_logits.
// 1 block per batch, 1024 threads, 8 elems/thread.
// ---------------------------------------------------------------------------
__global__ __launch_bounds__(1024) void softmax_kernel(const float* logits_in,
                                                       const float* __restrict__ gp,
                                                       float* p_out) {
    __shared__ float red_max[32];
    __shared__ float red_sum[32];
    int b   = blockIdx.x;
    int tid = threadIdx.x;
    const float* logits = logits_in ? logits_in : g_logits;

    float l[8];
    float mx = -INFINITY;
    #pragma unroll
    for (int k = 0; k < 8; k++) {
        l[k] = logits[b * NM + tid + k * 1024];
        mx = fmaxf(mx, l[k]);
    }
    #pragma unroll
    for (int off = 16; off; off >>= 1)
        mx = fmaxf(mx, __shfl_xor_sync(0xffffffffu, mx, off));
    if ((tid & 31) == 0) red_max[tid >> 5] = mx;
    __syncthreads();
    if (tid < 32) {
        float v = red_max[tid];
        #pragma unroll
        for (int off = 16; off; off >>= 1)
            v = fmaxf(v, __shfl_xor_sync(0xffffffffu, v, off));
        red_max[tid] = v;
    }
    __syncthreads();
    mx = red_max[0];

    float sum = 0.0f;
    #pragma unroll
    for (int k = 0; k < 8; k++) {
        l[k] = __expf(l[k] - mx);
        sum += l[k];
    }
    #pragma unroll
    for (int off = 16; off; off >>= 1)
        sum += __shfl_xor_sync(0xffffffffu, sum, off);
    if ((tid & 31) == 0) red_sum[tid >> 5] = sum;
    __syncthreads();
    if (tid < 32) {
        float v = red_sum[tid];
        #pragma unroll
        for (int off = 16; off; off >>= 1)
            v += __shfl_xor_sync(0xffffffffu, v, off);
        red_sum[tid] = v;
    }
    __syncthreads();
    float inv = 1.0f / red_sum[0];

    #pragma unroll
    for (int k = 0; k < 8; k++) {
        int idx = b * NM + tid + k * 1024;
        float p = l[k] * inv;
        if (p_out) p_out[idx] = p;
        g_w[idx] = p * gp[idx];
    }
}

// ---------------------------------------------------------------------------
// pass_c: ok[b,d] += sum over 64-row chunk of w[b,m] * S[b,m,d]
// 128 threads (4 warps) -> 16 blocks/SM resident -> all 1024 blocks in ONE wave.
// Each warp: 16 rows, 2 float4 per row -> 32 float4 loads in flight per thread.
// 4-warp smem reduction, then 2 atomics/thread (256/block).
// which: 0 -> g_ok0, 1 -> g_ok1.
// ---------------------------------------------------------------------------
__global__ __launch_bounds__(128) void pass_c(const float* __restrict__ S, int which) {
    __shared__ float ws[64];
    __shared__ float red[4][256];
    int tid  = threadIdx.x;
    int warp = tid >> 5;
    int lane = tid & 31;
    int b  = blockIdx.x >> 7;                 // 128 chunks per batch
    int m0 = (blockIdx.x & 127) * 64;

    if (tid < 64)
        ws[tid] = g_w[b * NM + m0 + tid];
    __syncthreads();

    const float* base = S + ((long)b * NM + m0) * ND;
    float4 accA = make_float4(0.f, 0.f, 0.f, 0.f);
    float4 accC = make_float4(0.f, 0.f, 0.f, 0.f);

    #pragma unroll
    for (int i = 0; i < 16; i++) {
        int r = warp + 4 * i;                 // warp-interleaved rows
        float wgt = ws[r];
        const float4* Sr = (const float4*)(base + (long)r * ND);
        float4 a = Sr[lane];
        float4 c = Sr[lane + 32];
        accA.x = fmaf(wgt, a.x, accA.x);
        accA.y = fmaf(wgt, a.y, accA.y);
        accA.z = fmaf(wgt, a.z, accA.z);
        accA.w = fmaf(wgt, a.w, accA.w);
        accC.x = fmaf(wgt, c.x, accC.x);
        accC.y = fmaf(wgt, c.y, accC.y);
        accC.z = fmaf(wgt, c.z, accC.z);
        accC.w = fmaf(wgt, c.w, accC.w);
    }

    ((float4*)&red[warp][lane * 4])[0]       = accA;
    ((float4*)&red[warp][128 + lane * 4])[0] = accC;
    __syncthreads();

    float* ok = which ? g_ok1 : g_ok0;
    float s0 = red[0][tid]       + red[1][tid]       + red[2][tid]       + red[3][tid];
    float s1 = red[0][tid + 128] + red[1][tid + 128] + red[2][tid + 128] + red[3][tid + 128];
    atomicAdd(&ok[b * ND + tid],       s0);
    atomicAdd(&ok[b * ND + tid + 128], s1);
}

// ---------------------------------------------------------------------------
// launcher — pure kernel launches, no host API calls (graph-capture safe).
// ---------------------------------------------------------------------------
extern "C" void kernel_launch(void* const* d_in, const int* in_sizes, int n_in,
                              void* d_out, int out_size) {
    // Map inputs by element count: 2048=query, 65536=gp, rest=m_story
    const float* q  = nullptr;
    const float* gp = nullptr;
    const float* S  = nullptr;
    for (int i = 0; i < n_in; i++) {
        if (in_sizes[i] == NB * ND)      q  = (const float*)d_in[i];
        else if (in_sizes[i] == NB * NM) gp = (const float*)d_in[i];
        else                             S  = (const float*)d_in[i];
    }

    float* out   = (float*)d_out;
    float* p_out = out;            // prob_soft   -> first 65536
    float* l_out = out + NB * NM;  // prob_logits -> second 65536

    init_kernel<<<2, 1024>>>();

    // hop 0
    pass_a<<<4096, 256>>>(S,             gp, q, 0, nullptr);
    softmax_kernel<<<NB, 1024>>>(nullptr, gp, nullptr);
    pass_c<<<1024, 128>>>(S + SLICE, 0);

    // hop 1
    pass_a<<<4096, 256>>>(S + SLICE,     gp, q, 1, nullptr);
    softmax_kernel<<<NB, 1024>>>(nullptr, gp, nullptr);
    pass_c<<<1024, 128>>>(S + 2 * SLICE, 1);

    // hop 2 — outputs only need logits + softmax; m_story[3] never touched.
    pass_a<<<4096, 256>>>(S + 2 * SLICE, gp, q, 2, l_out);
    softmax_kernel<<<NB, 1024>>>(l_out,   gp, p_out);
}